// round 13
// baseline (speedup 1.0000x reference)
#include <cuda_runtime.h>
#include <math.h>
#include <stddef.h>

#define BB     4
#define SS     1024
#define DMODEL 512
#define HH     8
#define DHEAD  64
#define DFF    2048
#define BHTOT  (BB*HH)          // 32
#define MROWS  (BB*SS)          // 4096
#define NCHUNK 64               // qkmax chunks per (b,h) (8x8 blocks)

// ---------------- scratch (static device globals: alloc-free) ----------------
__device__ float g_q[MROWS * DMODEL];
__device__ float g_k[MROWS * DMODEL];
__device__ float g_v[MROWS * DMODEL];
__device__ float g_o[MROWS * DMODEL];
__device__ float g_t0[MROWS * DMODEL];
__device__ float g_out1[MROWS * DMODEL];
__device__ float g_ffn1[MROWS * DFF];
__device__ float g_h[MROWS * DMODEL];
__device__ float g_pm[BHTOT * NCHUNK];
__device__ float g_ps[BHTOT * 8];                // fused-attn per-block Z partials
__device__ float g_M[BHTOT];
__device__ float g_scale[BHTOT];
__device__ float g_nz;

// ---------------- helpers ----------------
__device__ __forceinline__ unsigned f2tf(float x) {
    unsigned r; asm("cvt.rna.tf32.f32 %0, %1;" : "=r"(r) : "f"(x)); return r;
}
__device__ __forceinline__ void split_tf(float x, unsigned& hi, unsigned& lo) {
    hi = f2tf(x);
    lo = f2tf(x - __uint_as_float(hi));
}
__device__ __forceinline__ void mma_tf32(float c[4], const unsigned a[4], const unsigned b[2]) {
    asm volatile(
        "mma.sync.aligned.m16n8k8.row.col.f32.tf32.tf32.f32 "
        "{%0,%1,%2,%3}, {%4,%5,%6,%7}, {%8,%9}, {%0,%1,%2,%3};\n"
        : "+f"(c[0]), "+f"(c[1]), "+f"(c[2]), "+f"(c[3])
        : "r"(a[0]), "r"(a[1]), "r"(a[2]), "r"(a[3]), "r"(b[0]), "r"(b[1]));
}

// FMA-pipe exp: x <= ~0, magic-number rint + deg-5 poly of 2^f. rel err ~3e-6.
__device__ __forceinline__ float fast_exp(float x) {
    x = fmaxf(x, -80.f);
    float y = x * 1.442695041f;
    float z = y + 12582912.f;                        // 2^23 + 2^22
    int   n = __float_as_int(z) - 0x4B400000;
    float f = y - (z - 12582912.f);                  // [-0.5, 0.5]
    float p = 1.3333558e-3f;
    p = fmaf(p, f, 9.6181291e-3f);
    p = fmaf(p, f, 5.5504109e-2f);
    p = fmaf(p, f, 2.4022651e-1f);
    p = fmaf(p, f, 6.9314718e-1f);
    p = fmaf(p, f, 1.0f);
    return __int_as_float((n + 127) << 23) * p;
}

// ---------------- count_nonzero(protok[0]) ----------------
__global__ void count_nz_kernel(const int* __restrict__ protok) {
    __shared__ int cnt[256];
    int t = threadIdx.x;
    int c = 0;
    for (int i = t; i < SS; i += 256) c += (protok[i] != 0);
    cnt[t] = c; __syncthreads();
    for (int off = 128; off; off >>= 1) {
        if (t < off) cnt[t] += cnt[t + off];
        __syncthreads();
    }
    if (t == 0) g_nz = (float)cnt[0];
}

// ---------------- tf32 tensor-core GEMM: C = act(scaleA(A)[4096xK] * B[KxN] + bias) ----------------
template <bool RELU, bool SCALEA>
__global__ void __launch_bounds__(256) gemm_tf32(
    const float* __restrict__ A,
    const float* __restrict__ B0, const float* __restrict__ bias0, float* __restrict__ C0,
    const float* __restrict__ B1, const float* __restrict__ bias1, float* __restrict__ C1,
    const float* __restrict__ B2, const float* __restrict__ bias2, float* __restrict__ C2,
    int N, int K, const float* __restrict__ ascale)
{
    __shared__ unsigned As[128][36];     // [m][k]
    __shared__ unsigned Bs[32][136];     // [k][n]

    const float* Bm = B0; const float* bias = bias0; float* C = C0;
    if (blockIdx.z == 1) { Bm = B1; bias = bias1; C = C1; }
    else if (blockIdx.z == 2) { Bm = B2; bias = bias2; C = C2; }

    const int tid = threadIdx.x;
    const int wid = tid >> 5, lane = tid & 31;
    const int g = lane >> 2, t4 = lane & 3;
    const int warpM = wid & 1, warpN = wid >> 1;     // 2 x 4
    const int row0 = blockIdx.y * 128;
    const int col0 = blockIdx.x * 128;

    const int arow = tid >> 3;           // 0..31 (+i*32)
    const int acol = (tid & 7) * 4;
    const int brow = tid >> 5;           // 0..7 (+i*8)
    const int bcol = (tid & 31) * 4;

    float4 ra[4], rb[4];
    float acc[4][4][4];
    #pragma unroll
    for (int mi = 0; mi < 4; mi++)
        #pragma unroll
        for (int nj = 0; nj < 4; nj++)
            #pragma unroll
            for (int c = 0; c < 4; c++) acc[mi][nj][c] = 0.f;

    auto loadG = [&](int k0) {
        #pragma unroll
        for (int i = 0; i < 4; i++)
            ra[i] = *(const float4*)(A + (size_t)(row0 + arow + i * 32) * K + k0 + acol);
        if (SCALEA) {
            const float s = ascale[((row0 >> 10) << 3) + ((k0 + acol) >> 6)];
            #pragma unroll
            for (int i = 0; i < 4; i++) {
                ra[i].x *= s; ra[i].y *= s; ra[i].z *= s; ra[i].w *= s;
            }
        }
        #pragma unroll
        for (int i = 0; i < 4; i++)
            rb[i] = *(const float4*)(Bm + (size_t)(k0 + brow + i * 8) * N + col0 + bcol);
    };
    auto storeS = [&]() {
        #pragma unroll
        for (int i = 0; i < 4; i++) {
            uint4 u;
            u.x = f2tf(ra[i].x); u.y = f2tf(ra[i].y); u.z = f2tf(ra[i].z); u.w = f2tf(ra[i].w);
            *(uint4*)&As[arow + i * 32][acol] = u;
        }
        #pragma unroll
        for (int i = 0; i < 4; i++) {
            uint4 u;
            u.x = f2tf(rb[i].x); u.y = f2tf(rb[i].y); u.z = f2tf(rb[i].z); u.w = f2tf(rb[i].w);
            *(uint4*)&Bs[brow + i * 8][bcol] = u;
        }
    };

    loadG(0); storeS(); __syncthreads();

    for (int k0 = 0; k0 < K; k0 += 32) {
        const bool more = (k0 + 32) < K;
        if (more) loadG(k0 + 32);
        #pragma unroll
        for (int ks = 0; ks < 4; ks++) {
            const int kb = ks * 8;
            unsigned afr[4][4], bfr[4][2];
            #pragma unroll
            for (int mi = 0; mi < 4; mi++) {
                const int rm = warpM * 64 + mi * 16;
                afr[mi][0] = As[rm + g][kb + t4];
                afr[mi][1] = As[rm + g + 8][kb + t4];
                afr[mi][2] = As[rm + g][kb + t4 + 4];
                afr[mi][3] = As[rm + g + 8][kb + t4 + 4];
            }
            #pragma unroll
            for (int nj = 0; nj < 4; nj++) {
                const int cn = warpN * 32 + nj * 8;
                bfr[nj][0] = Bs[kb + t4][cn + g];
                bfr[nj][1] = Bs[kb + t4 + 4][cn + g];
            }
            #pragma unroll
            for (int mi = 0; mi < 4; mi++)
                #pragma unroll
                for (int nj = 0; nj < 4; nj++)
                    mma_tf32(acc[mi][nj], afr[mi], bfr[nj]);
        }
        __syncthreads();
        if (more) { storeS(); __syncthreads(); }
    }

    #pragma unroll
    for (int mi = 0; mi < 4; mi++) {
        const int r = row0 + warpM * 64 + mi * 16 + g;
        #pragma unroll
        for (int nj = 0; nj < 4; nj++) {
            const int c = col0 + warpN * 32 + nj * 8 + 2 * t4;
            const float b0 = bias[c], b1 = bias[c + 1];
            float v0 = acc[mi][nj][0] + b0, v1 = acc[mi][nj][1] + b1;
            float v2 = acc[mi][nj][2] + b0, v3 = acc[mi][nj][3] + b1;
            if (RELU) {
                v0 = fmaxf(v0, 0.f); v1 = fmaxf(v1, 0.f);
                v2 = fmaxf(v2, 0.f); v3 = fmaxf(v3, 0.f);
            }
            float2 p0; p0.x = v0; p0.y = v1;
            float2 p1; p1.x = v2; p1.y = v3;
            *(float2*)&C[(size_t)r * N + c] = p0;
            *(float2*)&C[(size_t)(r + 8) * N + c] = p1;
        }
    }
}

// ---------------- pass 1: block max of q.k/8, single tf32, no mask, no store ----------------
// grid (8, 8, 32): 128x128 tile, 8 warps (2x4), warp tile 64x32.
__global__ void __launch_bounds__(256) qkmax_tf32(
    const float* __restrict__ q, const float* __restrict__ kmat)
{
    __shared__ unsigned Qs[128][36];   // [i][d] chunk of 32
    __shared__ unsigned Ks[128][36];   // [j][d]
    __shared__ float red_m[256];

    const int bh = blockIdx.z, b = bh >> 3, h = bh & 7;
    const int i0 = blockIdx.y * 128, j0 = blockIdx.x * 128;
    const int tid = threadIdx.x;
    const int wid = tid >> 5, lane = tid & 31;
    const int g = lane >> 2, t4 = lane & 3;
    const int warpM = wid & 1, warpN = wid >> 1;

    const float* qb = q + (size_t)(b * SS + i0) * DMODEL + h * 64;
    const float* kb = kmat + (size_t)(b * SS + j0) * DMODEL + h * 64;

    const int row = tid >> 1;            // 0..127
    const int c0 = (tid & 1) * 16;       // +it*4

    float acc[4][4][4];
    #pragma unroll
    for (int mi = 0; mi < 4; mi++)
        #pragma unroll
        for (int nj = 0; nj < 4; nj++)
            #pragma unroll
            for (int c = 0; c < 4; c++) acc[mi][nj][c] = 0.f;

    for (int k0 = 0; k0 < 64; k0 += 32) {
        #pragma unroll
        for (int it = 0; it < 4; it++) {
            float4 qv = *(const float4*)(qb + (size_t)row * DMODEL + k0 + c0 + it * 4);
            float4 kv = *(const float4*)(kb + (size_t)row * DMODEL + k0 + c0 + it * 4);
            uint4 uq, uk;
            uq.x = f2tf(qv.x); uq.y = f2tf(qv.y); uq.z = f2tf(qv.z); uq.w = f2tf(qv.w);
            uk.x = f2tf(kv.x); uk.y = f2tf(kv.y); uk.z = f2tf(kv.z); uk.w = f2tf(kv.w);
            *(uint4*)&Qs[row][c0 + it * 4] = uq;
            *(uint4*)&Ks[row][c0 + it * 4] = uk;
        }
        __syncthreads();
        #pragma unroll
        for (int ks = 0; ks < 4; ks++) {
            const int kb8 = ks * 8;
            unsigned afr[4][4], bfr[4][2];
            #pragma unroll
            for (int mi = 0; mi < 4; mi++) {
                const int rm = warpM * 64 + mi * 16;
                afr[mi][0] = Qs[rm + g][kb8 + t4];
                afr[mi][1] = Qs[rm + g + 8][kb8 + t4];
                afr[mi][2] = Qs[rm + g][kb8 + t4 + 4];
                afr[mi][3] = Qs[rm + g + 8][kb8 + t4 + 4];
            }
            #pragma unroll
            for (int nj = 0; nj < 4; nj++) {
                const int cn = warpN * 32 + nj * 8;
                bfr[nj][0] = Ks[cn + g][kb8 + t4];
                bfr[nj][1] = Ks[cn + g][kb8 + t4 + 4];
            }
            #pragma unroll
            for (int mi = 0; mi < 4; mi++)
                #pragma unroll
                for (int nj = 0; nj < 4; nj++)
                    mma_tf32(acc[mi][nj], afr[mi], bfr[nj]);
        }
        __syncthreads();
    }

    float pm = -1e30f;
    #pragma unroll
    for (int mi = 0; mi < 4; mi++)
        #pragma unroll
        for (int nj = 0; nj < 4; nj++)
            #pragma unroll
            for (int c = 0; c < 4; c++)
                pm = fmaxf(pm, acc[mi][nj][c]);
    pm *= 0.125f;

    red_m[tid] = pm; __syncthreads();
    for (int off = 128; off; off >>= 1) {
        if (tid < off) red_m[tid] = fmaxf(red_m[tid], red_m[tid + off]);
        __syncthreads();
    }
    if (tid == 0)
        g_pm[bh * NCHUNK + blockIdx.y * 8 + blockIdx.x] = red_m[0];
}

// ---------------- max final: M[bh] = max over chunks ----------------
__global__ void __launch_bounds__(NCHUNK) max_final_kernel() {
    const int bh = blockIdx.x, tid = threadIdx.x;
    __shared__ float sm[NCHUNK];
    sm[tid] = g_pm[bh * NCHUNK + tid];
    __syncthreads();
    for (int off = NCHUNK / 2; off; off >>= 1) {
        if (tid < off) sm[tid] = fmaxf(sm[tid], sm[tid + off]);
        __syncthreads();
    }
    if (tid == 0) g_M[bh] = sm[0];
}

// ---------------- pass 2: fused attention (no logits materialization) ----------------
// Per (bh, i-tile of 128): K_i resident (hi/lo). Loop j in steps of 32:
//   S[j,i] = Q_j . K_i (3xTF32), P = fast_exp(S/8 - 1e9*mask[j,i] - M), Z partial,
//   O[i,d] += P^T @ V_j (tf32). O unscaled; nz/Z applied later in wo-GEMM.
__global__ void __launch_bounds__(256) fused_attn_tf32(
    const float* __restrict__ q, const float* __restrict__ kmat,
    const float* __restrict__ v, const float* __restrict__ mask,
    float* __restrict__ o)
{
    extern __shared__ unsigned smu[];
    unsigned* KH = smu;                    // [128][68]
    unsigned* KL = KH + 128 * 68;
    unsigned* QH = KL + 128 * 68;          // [32][68]
    unsigned* QL = QH + 32 * 68;
    unsigned* PS = QL + 32 * 68;           // [32][132]  (tf32 P, [j][i])
    unsigned* VS = PS + 32 * 132;          // [32][72]   (tf32 V, [j][d])
    __shared__ float red[256];

    const int bh = blockIdx.y, b = bh >> 3, h = bh & 7;
    const int i0 = blockIdx.x * 128;
    const float Mb = g_M[bh];

    const int tid = threadIdx.x;
    const int wid = tid >> 5, lane = tid & 31;
    const int g = lane >> 2, t4 = lane & 3;
    const int wA = wid & 1, wB = wid >> 1;   // S: j-half / i-quarter; O: i-half / d-quarter

    const float* qb = q + (size_t)(b * SS) * DMODEL + h * 64;
    const float* kb = kmat + (size_t)(b * SS + i0) * DMODEL + h * 64;
    const float* vb = v + (size_t)(b * SS) * DMODEL + h * 64;
    const float* mb = mask + (size_t)b * SS * SS;

    // resident K_i tile -> KH/KL
    {
        const int row = tid >> 1;
        const int c0 = (tid & 1) * 32;
        #pragma unroll
        for (int it = 0; it < 8; it++) {
            float4 kv = *(const float4*)(kb + (size_t)row * DMODEL + c0 + it * 4);
            unsigned h0, l0, h1, l1, h2, l2, h3, l3;
            split_tf(kv.x, h0, l0); split_tf(kv.y, h1, l1);
            split_tf(kv.z, h2, l2); split_tf(kv.w, h3, l3);
            unsigned* ph = KH + row * 68 + c0 + it * 4;
            unsigned* pl = KL + row * 68 + c0 + it * 4;
            ph[0] = h0; ph[1] = h1; ph[2] = h2; ph[3] = h3;
            pl[0] = l0; pl[1] = l1; pl[2] = l2; pl[3] = l3;
        }
    }

    float acc_o[4][2][4];
    #pragma unroll
    for (int mi = 0; mi < 4; mi++)
        #pragma unroll
        for (int nj = 0; nj < 2; nj++)
            #pragma unroll
            for (int c = 0; c < 4; c++) acc_o[mi][nj][c] = 0.f;
    float psum = 0.f;

    const int qrow = tid >> 3;          // 0..31
    const int qcol = (tid & 7) * 4;     // +32 for second
    float4 rq[2], rv[2];
    float2 cm[8], nm[8];                // mask regs (cur / next): [nj*2 + half]

    // prologue: j-step 0 operands
    rq[0] = *(const float4*)(qb + (size_t)qrow * DMODEL + qcol);
    rq[1] = *(const float4*)(qb + (size_t)qrow * DMODEL + qcol + 32);
    rv[0] = *(const float4*)(vb + (size_t)qrow * DMODEL + qcol);
    rv[1] = *(const float4*)(vb + (size_t)qrow * DMODEL + qcol + 32);
    #pragma unroll
    for (int nj = 0; nj < 4; nj++) {
        const int ic = i0 + wB * 32 + nj * 8 + 2 * t4;
        cm[nj * 2 + 0] = *(const float2*)&mb[(size_t)(wA * 16 + g) * SS + ic];
        cm[nj * 2 + 1] = *(const float2*)&mb[(size_t)(wA * 16 + g + 8) * SS + ic];
    }

    for (int js = 0; js < 32; js++) {
        const int j0 = js * 32;
        __syncthreads();   // prev S-mma done with QH, prev O-mma done with PS/VS (and K ready 1st iter)

        // store Q (hi/lo) and V (tf32) tiles
        #pragma unroll
        for (int it = 0; it < 2; it++) {
            unsigned h0, l0, h1, l1, h2, l2, h3, l3;
            const float4 a = rq[it];
            split_tf(a.x, h0, l0); split_tf(a.y, h1, l1);
            split_tf(a.z, h2, l2); split_tf(a.w, h3, l3);
            unsigned* ph = QH + qrow * 68 + qcol + it * 32;
            unsigned* pl = QL + qrow * 68 + qcol + it * 32;
            ph[0] = h0; ph[1] = h1; ph[2] = h2; ph[3] = h3;
            pl[0] = l0; pl[1] = l1; pl[2] = l2; pl[3] = l3;
            const float4 w = rv[it];
            uint4 u;
            u.x = f2tf(w.x); u.y = f2tf(w.y); u.z = f2tf(w.z); u.w = f2tf(w.w);
            *(uint4*)(VS + qrow * 72 + qcol + it * 32) = u;
        }
        // prefetch next j-step operands
        if (js + 1 < 32) {
            const int jn = j0 + 32;
            rq[0] = *(const float4*)(qb + (size_t)(jn + qrow) * DMODEL + qcol);
            rq[1] = *(const float4*)(qb + (size_t)(jn + qrow) * DMODEL + qcol + 32);
            rv[0] = *(const float4*)(vb + (size_t)(jn + qrow) * DMODEL + qcol);
            rv[1] = *(const float4*)(vb + (size_t)(jn + qrow) * DMODEL + qcol + 32);
            #pragma unroll
            for (int nj = 0; nj < 4; nj++) {
                const int ic = i0 + wB * 32 + nj * 8 + 2 * t4;
                nm[nj * 2 + 0] = *(const float2*)&mb[(size_t)(jn + wA * 16 + g) * SS + ic];
                nm[nj * 2 + 1] = *(const float2*)&mb[(size_t)(jn + wA * 16 + g + 8) * SS + ic];
            }
        }
        __syncthreads();

        // S-mma: S[j(32), i(128)] over d=64 (8 k-steps), 3xTF32
        float acc_s[4][4];
        #pragma unroll
        for (int nj = 0; nj < 4; nj++)
            #pragma unroll
            for (int c = 0; c < 4; c++) acc_s[nj][c] = 0.f;

        #pragma unroll
        for (int ks = 0; ks < 8; ks++) {
            const int kb8 = ks * 8;
            const int jm = wA * 16;
            unsigned ah[4], al[4];
            ah[0] = QH[(jm + g) * 68 + kb8 + t4];
            ah[1] = QH[(jm + g + 8) * 68 + kb8 + t4];
            ah[2] = QH[(jm + g) * 68 + kb8 + t4 + 4];
            ah[3] = QH[(jm + g + 8) * 68 + kb8 + t4 + 4];
            al[0] = QL[(jm + g) * 68 + kb8 + t4];
            al[1] = QL[(jm + g + 8) * 68 + kb8 + t4];
            al[2] = QL[(jm + g) * 68 + kb8 + t4 + 4];
            al[3] = QL[(jm + g + 8) * 68 + kb8 + t4 + 4];
            #pragma unroll
            for (int nj = 0; nj < 4; nj++) {
                const int cn = wB * 32 + nj * 8;
                unsigned bh2[2], bl2[2];
                bh2[0] = KH[(cn + g) * 68 + kb8 + t4];
                bh2[1] = KH[(cn + g) * 68 + kb8 + t4 + 4];
                bl2[0] = KL[(cn + g) * 68 + kb8 + t4];
                bl2[1] = KL[(cn + g) * 68 + kb8 + t4 + 4];
                mma_tf32(acc_s[nj], ah, bl2);
                mma_tf32(acc_s[nj], al, bh2);
                mma_tf32(acc_s[nj], ah, bh2);
            }
        }

        // epilogue: mask + exp -> PS, Z partial
        #pragma unroll
        for (int nj = 0; nj < 4; nj++) {
            const int iloc = wB * 32 + nj * 8 + 2 * t4;
            const int jA = wA * 16 + g, jB = jA + 8;
            const float2 m0 = cm[nj * 2 + 0];
            const float2 m1 = cm[nj * 2 + 1];
            float e0 = fast_exp(fmaf(acc_s[nj][0], 0.125f, fmaf(m0.x, -1e9f, -Mb)));
            float e1 = fast_exp(fmaf(acc_s[nj][1], 0.125f, fmaf(m0.y, -1e9f, -Mb)));
            float e2 = fast_exp(fmaf(acc_s[nj][2], 0.125f, fmaf(m1.x, -1e9f, -Mb)));
            float e3 = fast_exp(fmaf(acc_s[nj][3], 0.125f, fmaf(m1.y, -1e9f, -Mb)));
            psum += (e0 + e1) + (e2 + e3);
            uint2 u0; u0.x = f2tf(e0); u0.y = f2tf(e1);
            uint2 u1; u1.x = f2tf(e2); u1.y = f2tf(e3);
            *(uint2*)(PS + jA * 132 + iloc) = u0;
            *(uint2*)(PS + jB * 132 + iloc) = u1;
        }
        #pragma unroll
        for (int x = 0; x < 8; x++) cm[x] = nm[x];
        __syncthreads();

        // O-mma: O[i(128), d(64)] += P^T V, k=j (4 k-steps of 8)
        #pragma unroll
        for (int ks = 0; ks < 4; ks++) {
            const int kb8 = ks * 8;
            unsigned afr[4][4], bfr[2][2];
            #pragma unroll
            for (int mi = 0; mi < 4; mi++) {
                const int rm = wA * 64 + mi * 16;
                afr[mi][0] = PS[(kb8 + t4) * 132 + rm + g];
                afr[mi][1] = PS[(kb8 + t4) * 132 + rm + g + 8];
                afr[mi][2] = PS[(kb8 + t4 + 4) * 132 + rm + g];
                afr[mi][3] = PS[(kb8 + t4 + 4) * 132 + rm + g + 8];
            }
            #pragma unroll
            for (int nj = 0; nj < 2; nj++) {
                const int cn = wB * 16 + nj * 8;
                bfr[nj][0] = VS[(kb8 + t4) * 72 + cn + g];
                bfr[nj][1] = VS[(kb8 + t4 + 4) * 72 + cn + g];
            }
            #pragma unroll
            for (int mi = 0; mi < 4; mi++)
                #pragma unroll
                for (int nj = 0; nj < 2; nj++)
                    mma_tf32(acc_o[mi][nj], afr[mi], bfr[nj]);
        }
    }

    // Z partial reduce
    red[tid] = psum; __syncthreads();
    for (int off = 128; off; off >>= 1) {
        if (tid < off) red[tid] += red[tid + off];
        __syncthreads();
    }
    if (tid == 0) g_ps[bh * 8 + blockIdx.x] = red[0];

    // write unscaled O
    #pragma unroll
    for (int mi = 0; mi < 4; mi++) {
        const int i = i0 + wA * 64 + mi * 16 + g;
        #pragma unroll
        for (int nj = 0; nj < 2; nj++) {
            const int c = wB * 16 + nj * 8 + 2 * t4;
            float2 p0; p0.x = acc_o[mi][nj][0]; p0.y = acc_o[mi][nj][1];
            float2 p1; p1.x = acc_o[mi][nj][2]; p1.y = acc_o[mi][nj][3];
            *(float2*)&o[(size_t)(b * SS + i) * DMODEL + h * 64 + c] = p0;
            *(float2*)&o[(size_t)(b * SS + i + 8) * DMODEL + h * 64 + c] = p1;
        }
    }
}

// ---------------- scale final: g_scale[bh] = nz / Z ----------------
__global__ void __launch_bounds__(32) scale_final_kernel() {
    const int bh = blockIdx.x;
    const int lane = threadIdx.x;
    float s = (lane < 8) ? g_ps[bh * 8 + lane] : 0.f;
    #pragma unroll
    for (int off = 4; off; off >>= 1)
        s += __shfl_down_sync(0xFFFFFFFF, s, off);
    if (lane == 0) g_scale[bh] = g_nz / s;
}

// ---------------- out = LayerNorm(a + r) * gamma + beta ----------------
__global__ void __launch_bounds__(256) add_ln_kernel(
    const float* __restrict__ a, const float* __restrict__ r,
    const float* __restrict__ gam, const float* __restrict__ bet,
    float* __restrict__ o)
{
    __shared__ float red[256];
    const int row = blockIdx.x, t = threadIdx.x;
    const size_t base = (size_t)row * DMODEL;
    float y0 = a[base + t] + r[base + t];
    float y1 = a[base + t + 256] + r[base + t + 256];
    red[t] = y0 + y1; __syncthreads();
    for (int off = 128; off; off >>= 1) {
        if (t < off) red[t] += red[t + off];
        __syncthreads();
    }
    float mean = red[0] * (1.0f / DMODEL);
    __syncthreads();
    float d0 = y0 - mean, d1 = y1 - mean;
    red[t] = d0 * d0 + d1 * d1; __syncthreads();
    for (int off = 128; off; off >>= 1) {
        if (t < off) red[t] += red[t + off];
        __syncthreads();
    }
    float inv = rsqrtf(red[0] * (1.0f / DMODEL) + 1e-9f);
    o[base + t] = d0 * inv * gam[t] + bet[t];
    o[base + t + 256] = d1 * inv * gam[t + 256] + bet[t + 256];
}

// ---------------- host launcher ----------------
extern "C" void kernel_launch(void* const* d_in, const int* in_sizes, int n_in,
                              void* d_out, int out_size)
{
    (void)in_sizes; (void)n_in; (void)out_size;
    const float* x     = (const float*)d_in[0];
    const float* mask  = (const float*)d_in[1];
    const int*   ptk   = (const int*)d_in[2];
    const float* wq    = (const float*)d_in[3];
    const float* bq    = (const float*)d_in[4];
    const float* wk    = (const float*)d_in[5];
    const float* bk    = (const float*)d_in[6];
    const float* wv    = (const float*)d_in[7];
    const float* bv    = (const float*)d_in[8];
    const float* wo    = (const float*)d_in[9];
    const float* bo    = (const float*)d_in[10];
    const float* w1    = (const float*)d_in[11];
    const float* b1    = (const float*)d_in[12];
    const float* w2    = (const float*)d_in[13];
    const float* b2    = (const float*)d_in[14];
    const float* ln1g  = (const float*)d_in[15];
    const float* ln1b  = (const float*)d_in[16];
    const float* ln2g  = (const float*)d_in[17];
    const float* ln2b  = (const float*)d_in[18];
    float* out = (float*)d_out;

    float *q, *k, *v, *o, *t0, *out1, *ffn1, *hbuf, *scl;
    cudaGetSymbolAddress((void**)&q,    g_q);
    cudaGetSymbolAddress((void**)&k,    g_k);
    cudaGetSymbolAddress((void**)&v,    g_v);
    cudaGetSymbolAddress((void**)&o,    g_o);
    cudaGetSymbolAddress((void**)&t0,   g_t0);
    cudaGetSymbolAddress((void**)&out1, g_out1);
    cudaGetSymbolAddress((void**)&ffn1, g_ffn1);
    cudaGetSymbolAddress((void**)&hbuf, g_h);
    cudaGetSymbolAddress((void**)&scl,  g_scale);

    const int FUSED_SMEM = (128 * 68 * 2 + 32 * 68 * 2 + 32 * 132 + 32 * 72) * 4;
    cudaFuncSetAttribute(fused_attn_tf32,
                         cudaFuncAttributeMaxDynamicSharedMemorySize, FUSED_SMEM);

    count_nz_kernel<<<1, 256>>>(ptk);

    const dim3 gqkv(DMODEL / 128, MROWS / 128, 3);   // (4, 32, 3)
    const dim3 g512(DMODEL / 128, MROWS / 128, 1);   // (4, 32)
    const dim3 gff(DFF / 128, MROWS / 128, 1);       // (16, 32)
    const dim3 gmax(SS / 128, SS / 128, BHTOT);      // (8, 8, 32)
    const dim3 gfa(SS / 128, BHTOT);                 // (8, 32)

    const float* hin = x;
    for (int l = 0; l < 2; l++) {
        float* hout = (l == 1) ? out : hbuf;

        gemm_tf32<false, false><<<gqkv, 256>>>(hin,
            wq, bq, q,  wk, bk, k,  wv, bv, v,  DMODEL, DMODEL, nullptr);

        qkmax_tf32<<<gmax, 256>>>(q, k);
        max_final_kernel<<<BHTOT, NCHUNK>>>();
        fused_attn_tf32<<<gfa, 256, FUSED_SMEM>>>(q, k, v, mask, o);
        scale_final_kernel<<<BHTOT, 32>>>();

        gemm_tf32<false, true><<<g512, 256>>>(o,
            wo, bo, t0,  wo, bo, t0,  wo, bo, t0,  DMODEL, DMODEL, scl);
        add_ln_kernel<<<MROWS, 256>>>(hin, t0, ln1g, ln1b, out1);

        gemm_tf32<true, false><<<gff, 256>>>(out1,
            w1, b1, ffn1,  w1, b1, ffn1,  w1, b1, ffn1,  DFF, DMODEL, nullptr);
        gemm_tf32<false, false><<<g512, 256>>>(ffn1,
            w2, b2, t0,  w2, b2, t0,  w2, b2, t0,  DMODEL, DFF, nullptr);
        add_ln_kernel<<<MROWS, 256>>>(out1, t0, ln2g, ln2b, hout);

        hin = hout;
    }
}

// round 17
// speedup vs baseline: 1.1722x; 1.1722x over previous
#include <cuda_runtime.h>
#include <math.h>
#include <stddef.h>

#define BB     4
#define SS     1024
#define DMODEL 512
#define HH     8
#define DHEAD  64
#define DFF    2048
#define BHTOT  (BB*HH)          // 32
#define MROWS  (BB*SS)          // 4096

// ---------------- scratch (static device globals: alloc-free) ----------------
__device__ float g_q[MROWS * DMODEL];
__device__ float g_k[MROWS * DMODEL];
__device__ float g_v[MROWS * DMODEL];
__device__ float g_o[MROWS * DMODEL];
__device__ float g_t0[MROWS * DMODEL];
__device__ float g_out1[MROWS * DMODEL];
__device__ float g_ffn1[MROWS * DFF];
__device__ float g_h[MROWS * DMODEL];
__device__ float g_pm[BHTOT * 16];               // [bh][0:8]=q sumsq max chunks, [8:16]=k
__device__ float g_ps[BHTOT * 8];                // fused-attn per-block Z partials
__device__ float g_scale[BHTOT];
__device__ float g_nz;

// ---------------- helpers ----------------
__device__ __forceinline__ unsigned f2tf(float x) {
    unsigned r; asm("cvt.rna.tf32.f32 %0, %1;" : "=r"(r) : "f"(x)); return r;
}
__device__ __forceinline__ void mma_tf32(float c[4], const unsigned a[4], const unsigned b[2]) {
    asm volatile(
        "mma.sync.aligned.m16n8k8.row.col.f32.tf32.tf32.f32 "
        "{%0,%1,%2,%3}, {%4,%5,%6,%7}, {%8,%9}, {%0,%1,%2,%3};\n"
        : "+f"(c[0]), "+f"(c[1]), "+f"(c[2]), "+f"(c[3])
        : "r"(a[0]), "r"(a[1]), "r"(a[2]), "r"(a[3]), "r"(b[0]), "r"(b[1]));
}
__device__ __forceinline__ void mma_bf16(float c[4], const unsigned a[4], const unsigned b[2]) {
    asm volatile(
        "mma.sync.aligned.m16n8k16.row.col.f32.bf16.bf16.f32 "
        "{%0,%1,%2,%3}, {%4,%5,%6,%7}, {%8,%9}, {%0,%1,%2,%3};\n"
        : "+f"(c[0]), "+f"(c[1]), "+f"(c[2]), "+f"(c[3])
        : "r"(a[0]), "r"(a[1]), "r"(a[2]), "r"(a[3]), "r"(b[0]), "r"(b[1]));
}
// pack (even, odd) floats into bf16x2 hi word + bf16x2 residual word.
// low half of word = even element (matches mma k-pair ordering).
__device__ __forceinline__ void split2(float e, float o, unsigned& hw, unsigned& lw) {
    asm("cvt.rn.bf16x2.f32 %0, %1, %2;" : "=r"(hw) : "f"(o), "f"(e));
    float he = __uint_as_float(hw << 16);
    float ho = __uint_as_float(hw & 0xFFFF0000u);
    float re = e - he, ro = o - ho;
    asm("cvt.rn.bf16x2.f32 %0, %1, %2;" : "=r"(lw) : "f"(ro), "f"(re));
}

// FMA-pipe exp: x <= ~0, magic-number rint + deg-5 poly of 2^f. rel err ~3e-6.
__device__ __forceinline__ float fast_exp(float x) {
    x = fmaxf(x, -80.f);
    float y = x * 1.442695041f;
    float z = y + 12582912.f;                        // 2^23 + 2^22
    int   n = __float_as_int(z) - 0x4B400000;
    float f = y - (z - 12582912.f);                  // [-0.5, 0.5]
    float p = 1.3333558e-3f;
    p = fmaf(p, f, 9.6181291e-3f);
    p = fmaf(p, f, 5.5504109e-2f);
    p = fmaf(p, f, 2.4022651e-1f);
    p = fmaf(p, f, 6.9314718e-1f);
    p = fmaf(p, f, 1.0f);
    return __int_as_float((n + 127) << 23) * p;
}

// ---------------- count_nonzero(protok[0]) ----------------
__global__ void count_nz_kernel(const int* __restrict__ protok) {
    __shared__ int cnt[256];
    int t = threadIdx.x;
    int c = 0;
    for (int i = t; i < SS; i += 256) c += (protok[i] != 0);
    cnt[t] = c; __syncthreads();
    for (int off = 128; off; off >>= 1) {
        if (t < off) cnt[t] += cnt[t + off];
        __syncthreads();
    }
    if (t == 0) g_nz = (float)cnt[0];
}

// ---------------- tf32 tensor-core GEMM: C = act(scaleA(A)[4096xK] * B[KxN] + bias) ----------------
template <bool RELU, bool SCALEA>
__global__ void __launch_bounds__(256) gemm_tf32(
    const float* __restrict__ A,
    const float* __restrict__ B0, const float* __restrict__ bias0, float* __restrict__ C0,
    const float* __restrict__ B1, const float* __restrict__ bias1, float* __restrict__ C1,
    const float* __restrict__ B2, const float* __restrict__ bias2, float* __restrict__ C2,
    int N, int K, const float* __restrict__ ascale)
{
    __shared__ unsigned As[128][36];     // [m][k]
    __shared__ unsigned Bs[32][136];     // [k][n]

    const float* Bm = B0; const float* bias = bias0; float* C = C0;
    if (blockIdx.z == 1) { Bm = B1; bias = bias1; C = C1; }
    else if (blockIdx.z == 2) { Bm = B2; bias = bias2; C = C2; }

    const int tid = threadIdx.x;
    const int wid = tid >> 5, lane = tid & 31;
    const int g = lane >> 2, t4 = lane & 3;
    const int warpM = wid & 1, warpN = wid >> 1;     // 2 x 4
    const int row0 = blockIdx.y * 128;
    const int col0 = blockIdx.x * 128;

    const int arow = tid >> 3;           // 0..31 (+i*32)
    const int acol = (tid & 7) * 4;
    const int brow = tid >> 5;           // 0..7 (+i*8)
    const int bcol = (tid & 31) * 4;

    float4 ra[4], rb[4];
    float acc[4][4][4];
    #pragma unroll
    for (int mi = 0; mi < 4; mi++)
        #pragma unroll
        for (int nj = 0; nj < 4; nj++)
            #pragma unroll
            for (int c = 0; c < 4; c++) acc[mi][nj][c] = 0.f;

    auto loadG = [&](int k0) {
        #pragma unroll
        for (int i = 0; i < 4; i++)
            ra[i] = *(const float4*)(A + (size_t)(row0 + arow + i * 32) * K + k0 + acol);
        if (SCALEA) {
            const float s = ascale[((row0 >> 10) << 3) + ((k0 + acol) >> 6)];
            #pragma unroll
            for (int i = 0; i < 4; i++) {
                ra[i].x *= s; ra[i].y *= s; ra[i].z *= s; ra[i].w *= s;
            }
        }
        #pragma unroll
        for (int i = 0; i < 4; i++)
            rb[i] = *(const float4*)(Bm + (size_t)(k0 + brow + i * 8) * N + col0 + bcol);
    };
    auto storeS = [&]() {
        #pragma unroll
        for (int i = 0; i < 4; i++) {
            uint4 u;
            u.x = f2tf(ra[i].x); u.y = f2tf(ra[i].y); u.z = f2tf(ra[i].z); u.w = f2tf(ra[i].w);
            *(uint4*)&As[arow + i * 32][acol] = u;
        }
        #pragma unroll
        for (int i = 0; i < 4; i++) {
            uint4 u;
            u.x = f2tf(rb[i].x); u.y = f2tf(rb[i].y); u.z = f2tf(rb[i].z); u.w = f2tf(rb[i].w);
            *(uint4*)&Bs[brow + i * 8][bcol] = u;
        }
    };

    loadG(0); storeS(); __syncthreads();

    for (int k0 = 0; k0 < K; k0 += 32) {
        const bool more = (k0 + 32) < K;
        if (more) loadG(k0 + 32);
        #pragma unroll
        for (int ks = 0; ks < 4; ks++) {
            const int kb = ks * 8;
            unsigned afr[4][4], bfr[4][2];
            #pragma unroll
            for (int mi = 0; mi < 4; mi++) {
                const int rm = warpM * 64 + mi * 16;
                afr[mi][0] = As[rm + g][kb + t4];
                afr[mi][1] = As[rm + g + 8][kb + t4];
                afr[mi][2] = As[rm + g][kb + t4 + 4];
                afr[mi][3] = As[rm + g + 8][kb + t4 + 4];
            }
            #pragma unroll
            for (int nj = 0; nj < 4; nj++) {
                const int cn = warpN * 32 + nj * 8;
                bfr[nj][0] = Bs[kb + t4][cn + g];
                bfr[nj][1] = Bs[kb + t4 + 4][cn + g];
            }
            #pragma unroll
            for (int mi = 0; mi < 4; mi++)
                #pragma unroll
                for (int nj = 0; nj < 4; nj++)
                    mma_tf32(acc[mi][nj], afr[mi], bfr[nj]);
        }
        __syncthreads();
        if (more) { storeS(); __syncthreads(); }
    }

    #pragma unroll
    for (int mi = 0; mi < 4; mi++) {
        const int r = row0 + warpM * 64 + mi * 16 + g;
        #pragma unroll
        for (int nj = 0; nj < 4; nj++) {
            const int c = col0 + warpN * 32 + nj * 8 + 2 * t4;
            const float b0 = bias[c], b1 = bias[c + 1];
            float v0 = acc[mi][nj][0] + b0, v1 = acc[mi][nj][1] + b1;
            float v2 = acc[mi][nj][2] + b0, v3 = acc[mi][nj][3] + b1;
            if (RELU) {
                v0 = fmaxf(v0, 0.f); v1 = fmaxf(v1, 0.f);
                v2 = fmaxf(v2, 0.f); v3 = fmaxf(v3, 0.f);
            }
            float2 p0; p0.x = v0; p0.y = v1;
            float2 p1; p1.x = v2; p1.y = v3;
            *(float2*)&C[(size_t)r * N + c] = p0;
            *(float2*)&C[(size_t)(r + 8) * N + c] = p1;
        }
    }
}

// ---------------- qk row-norm partials: M upper bound via Cauchy-Schwarz ----------------
// grid (8, BHTOT), 256 threads. chunk = 128 rows. Writes max row-sumsq per chunk.
__global__ void __launch_bounds__(256) qk_normmax_kernel(
    const float* __restrict__ q, const float* __restrict__ kmat)
{
    __shared__ float rq[256], rk[256];
    const int bh = blockIdx.y, b = bh >> 3, h = bh & 7;
    const int tid = threadIdx.x;
    const int row = blockIdx.x * 128 + (tid >> 1);
    const int d0 = (tid & 1) * 32;

    const float* qp = q + (size_t)(b * SS + row) * DMODEL + h * 64 + d0;
    const float* kp = kmat + (size_t)(b * SS + row) * DMODEL + h * 64 + d0;
    float sq = 0.f, sk = 0.f;
    #pragma unroll
    for (int it = 0; it < 8; it++) {
        float4 a = *(const float4*)(qp + it * 4);
        float4 c = *(const float4*)(kp + it * 4);
        sq += a.x * a.x + a.y * a.y + a.z * a.z + a.w * a.w;
        sk += c.x * c.x + c.y * c.y + c.z * c.z + c.w * c.w;
    }
    sq += __shfl_xor_sync(0xFFFFFFFF, sq, 1);
    sk += __shfl_xor_sync(0xFFFFFFFF, sk, 1);
    rq[tid] = sq; rk[tid] = sk; __syncthreads();
    for (int off = 128; off; off >>= 1) {
        if (tid < off) {
            rq[tid] = fmaxf(rq[tid], rq[tid + off]);
            rk[tid] = fmaxf(rk[tid], rk[tid + off]);
        }
        __syncthreads();
    }
    if (tid == 0) {
        g_pm[bh * 16 + blockIdx.x] = rq[0];
        g_pm[bh * 16 + 8 + blockIdx.x] = rk[0];
    }
}

// ---------------- fused attention (flash-style, S in 3xbf16) ----------------
// Per (bh, i-tile of 128): K_i resident (bf16 hi/lo pairs). Loop j in steps of 32:
//   S[j,i] = Q_j . K_i (3xbf16 m16n8k16), P = fast_exp(S/8 - 1e9*mask - M), Z partial,
//   O[i,d] += P^T @ V_j (tf32 m16n8k8). O unscaled; nz/Z applied in wo-GEMM.
__global__ void __launch_bounds__(256) fused_attn(
    const float* __restrict__ q, const float* __restrict__ kmat,
    const float* __restrict__ v, const float* __restrict__ mask,
    float* __restrict__ o)
{
    extern __shared__ unsigned smu[];
    unsigned* KH = smu;                    // [128][36] bf16x2 hi
    unsigned* KL = KH + 128 * 36;          // [128][36] bf16x2 lo
    unsigned* QH = KL + 128 * 36;          // [32][36]
    unsigned* QL = QH + 32 * 36;           // [32][36]
    unsigned* PS = QL + 32 * 36;           // [32][132]  (tf32 P, [j][i])
    unsigned* VS = PS + 32 * 132;          // [32][72]   (tf32 V, [j][d])
    __shared__ float red[256];
    __shared__ float mred[16];

    const int bh = blockIdx.y, b = bh >> 3, h = bh & 7;
    const int i0 = blockIdx.x * 128;

    const int tid = threadIdx.x;
    const int wid = tid >> 5, lane = tid & 31;
    const int g = lane >> 2, t4 = lane & 3;
    const int wA = wid & 1, wB = wid >> 1;

    // M = sqrt(max||q||^2 * max||k||^2) / 8  (Cauchy-Schwarz upper bound; exact cancel)
    if (tid < 16) mred[tid] = g_pm[bh * 16 + tid];
    __syncthreads();
    float mq = mred[0], mk = mred[8];
    #pragma unroll
    for (int x = 1; x < 8; x++) {
        mq = fmaxf(mq, mred[x]);
        mk = fmaxf(mk, mred[8 + x]);
    }
    const float Mb = sqrtf(mq * mk) * 0.125f;

    const float* qb = q + (size_t)(b * SS) * DMODEL + h * 64;
    const float* kb = kmat + (size_t)(b * SS + i0) * DMODEL + h * 64;
    const float* vb = v + (size_t)(b * SS) * DMODEL + h * 64;
    const float* mb = mask + (size_t)b * SS * SS;

    // resident K_i tile -> KH/KL (bf16 hi/lo pairs)
    {
        const int row = tid >> 1;
        const int dw = (tid & 1) * 16;      // word offset (32 d values)
        const int db = (tid & 1) * 32;
        #pragma unroll
        for (int it = 0; it < 4; it++) {
            float4 a = *(const float4*)(kb + (size_t)row * DMODEL + db + it * 8);
            float4 c = *(const float4*)(kb + (size_t)row * DMODEL + db + it * 8 + 4);
            uint4 uh, ul;
            split2(a.x, a.y, uh.x, ul.x);
            split2(a.z, a.w, uh.y, ul.y);
            split2(c.x, c.y, uh.z, ul.z);
            split2(c.z, c.w, uh.w, ul.w);
            *(uint4*)(KH + row * 36 + dw + it * 4) = uh;
            *(uint4*)(KL + row * 36 + dw + it * 4) = ul;
        }
    }

    float acc_o[4][2][4];
    #pragma unroll
    for (int mi = 0; mi < 4; mi++)
        #pragma unroll
        for (int nj = 0; nj < 2; nj++)
            #pragma unroll
            for (int c = 0; c < 4; c++) acc_o[mi][nj][c] = 0.f;
    float psum = 0.f;

    const int qrow = tid >> 3;          // 0..31
    const int qd = (tid & 7) * 8;       // d base (8 consecutive)
    float4 rq[2], rv[2];
    float2 cm[8], nm[8];

    // prologue: j-step 0 operands
    rq[0] = *(const float4*)(qb + (size_t)qrow * DMODEL + qd);
    rq[1] = *(const float4*)(qb + (size_t)qrow * DMODEL + qd + 4);
    rv[0] = *(const float4*)(vb + (size_t)qrow * DMODEL + qd);
    rv[1] = *(const float4*)(vb + (size_t)qrow * DMODEL + qd + 4);
    #pragma unroll
    for (int nj = 0; nj < 4; nj++) {
        const int ic = i0 + wB * 32 + nj * 8 + 2 * t4;
        cm[nj * 2 + 0] = *(const float2*)&mb[(size_t)(wA * 16 + g) * SS + ic];
        cm[nj * 2 + 1] = *(const float2*)&mb[(size_t)(wA * 16 + g + 8) * SS + ic];
    }

    for (int js = 0; js < 32; js++) {
        const int j0 = js * 32;
        __syncthreads();

        // store Q (bf16 hi/lo) and V (tf32) tiles
        {
            uint4 uh, ul;
            split2(rq[0].x, rq[0].y, uh.x, ul.x);
            split2(rq[0].z, rq[0].w, uh.y, ul.y);
            split2(rq[1].x, rq[1].y, uh.z, ul.z);
            split2(rq[1].z, rq[1].w, uh.w, ul.w);
            *(uint4*)(QH + qrow * 36 + (tid & 7) * 4) = uh;
            *(uint4*)(QL + qrow * 36 + (tid & 7) * 4) = ul;
            uint4 u0, u1;
            u0.x = f2tf(rv[0].x); u0.y = f2tf(rv[0].y);
            u0.z = f2tf(rv[0].z); u0.w = f2tf(rv[0].w);
            u1.x = f2tf(rv[1].x); u1.y = f2tf(rv[1].y);
            u1.z = f2tf(rv[1].z); u1.w = f2tf(rv[1].w);
            *(uint4*)(VS + qrow * 72 + qd) = u0;
            *(uint4*)(VS + qrow * 72 + qd + 4) = u1;
        }
        // prefetch next j-step operands
        if (js + 1 < 32) {
            const int jn = j0 + 32;
            rq[0] = *(const float4*)(qb + (size_t)(jn + qrow) * DMODEL + qd);
            rq[1] = *(const float4*)(qb + (size_t)(jn + qrow) * DMODEL + qd + 4);
            rv[0] = *(const float4*)(vb + (size_t)(jn + qrow) * DMODEL + qd);
            rv[1] = *(const float4*)(vb + (size_t)(jn + qrow) * DMODEL + qd + 4);
            #pragma unroll
            for (int nj = 0; nj < 4; nj++) {
                const int ic = i0 + wB * 32 + nj * 8 + 2 * t4;
                nm[nj * 2 + 0] = *(const float2*)&mb[(size_t)(jn + wA * 16 + g) * SS + ic];
                nm[nj * 2 + 1] = *(const float2*)&mb[(size_t)(jn + wA * 16 + g + 8) * SS + ic];
            }
        }
        __syncthreads();

        // S-mma: S[j(32), i(128)] over d=64 -> 4 ksteps of k16, 3xbf16
        float acc_s[4][4];
        #pragma unroll
        for (int nj = 0; nj < 4; nj++)
            #pragma unroll
            for (int c = 0; c < 4; c++) acc_s[nj][c] = 0.f;

        #pragma unroll
        for (int ks = 0; ks < 4; ks++) {
            const int w0 = ks * 8;           // 8 words = 16 k-values
            const int jm = wA * 16;
            unsigned ah[4], al[4];
            ah[0] = QH[(jm + g) * 36 + w0 + t4];
            ah[1] = QH[(jm + g + 8) * 36 + w0 + t4];
            ah[2] = QH[(jm + g) * 36 + w0 + t4 + 4];
            ah[3] = QH[(jm + g + 8) * 36 + w0 + t4 + 4];
            al[0] = QL[(jm + g) * 36 + w0 + t4];
            al[1] = QL[(jm + g + 8) * 36 + w0 + t4];
            al[2] = QL[(jm + g) * 36 + w0 + t4 + 4];
            al[3] = QL[(jm + g + 8) * 36 + w0 + t4 + 4];
            #pragma unroll
            for (int nj = 0; nj < 4; nj++) {
                const int cn = wB * 32 + nj * 8;
                unsigned bhf[2], blf[2];
                bhf[0] = KH[(cn + g) * 36 + w0 + t4];
                bhf[1] = KH[(cn + g) * 36 + w0 + t4 + 4];
                blf[0] = KL[(cn + g) * 36 + w0 + t4];
                blf[1] = KL[(cn + g) * 36 + w0 + t4 + 4];
                mma_bf16(acc_s[nj], ah, blf);
                mma_bf16(acc_s[nj], al, bhf);
                mma_bf16(acc_s[nj], ah, bhf);
            }
        }

        // epilogue: mask + exp -> PS, Z partial
        #pragma unroll
        for (int nj = 0; nj < 4; nj++) {
            const int iloc = wB * 32 + nj * 8 + 2 * t4;
            const int jA = wA * 16 + g, jB = jA + 8;
            const float2 m0 = cm[nj * 2 + 0];
            const float2 m1 = cm[nj * 2 + 1];
            float e0 = fast_exp(fmaf(acc_s[nj][0], 0.125f, fmaf(m0.x, -1e9f, -Mb)));
            float e1 = fast_exp(fmaf(acc_s[nj][1], 0.125f, fmaf(m0.y, -1e9f, -Mb)));
            float e2 = fast_exp(fmaf(acc_s[nj][2], 0.125f, fmaf(m1.x, -1e9f, -Mb)));
            float e3 = fast_exp(fmaf(acc_s[nj][3], 0.125f, fmaf(m1.y, -1e9f, -Mb)));
            psum += (e0 + e1) + (e2 + e3);
            uint2 u0; u0.x = f2tf(e0); u0.y = f2tf(e1);
            uint2 u1; u1.x = f2tf(e2); u1.y = f2tf(e3);
            *(uint2*)(PS + jA * 132 + iloc) = u0;
            *(uint2*)(PS + jB * 132 + iloc) = u1;
        }
        #pragma unroll
        for (int x = 0; x < 8; x++) cm[x] = nm[x];
        __syncthreads();

        // O-mma: O[i(128), d(64)] += P^T V, k=j (4 ksteps of k8, tf32)
        #pragma unroll
        for (int ks = 0; ks < 4; ks++) {
            const int kb8 = ks * 8;
            unsigned afr[4][4], bfr[2][2];
            #pragma unroll
            for (int mi = 0; mi < 4; mi++) {
                const int rm = wA * 64 + mi * 16;
                afr[mi][0] = PS[(kb8 + t4) * 132 + rm + g];
                afr[mi][1] = PS[(kb8 + t4) * 132 + rm + g + 8];
                afr[mi][2] = PS[(kb8 + t4 + 4) * 132 + rm + g];
                afr[mi][3] = PS[(kb8 + t4 + 4) * 132 + rm + g + 8];
            }
            #pragma unroll
            for (int nj = 0; nj < 2; nj++) {
                const int cn = wB * 16 + nj * 8;
                bfr[nj][0] = VS[(kb8 + t4) * 72 + cn + g];
                bfr[nj][1] = VS[(kb8 + t4 + 4) * 72 + cn + g];
            }
            #pragma unroll
            for (int mi = 0; mi < 4; mi++)
                #pragma unroll
                for (int nj = 0; nj < 2; nj++)
                    mma_tf32(acc_o[mi][nj], afr[mi], bfr[nj]);
        }
    }

    // Z partial reduce
    red[tid] = psum; __syncthreads();
    for (int off = 128; off; off >>= 1) {
        if (tid < off) red[tid] += red[tid + off];
        __syncthreads();
    }
    if (tid == 0) g_ps[bh * 8 + blockIdx.x] = red[0];

    // write unscaled O
    #pragma unroll
    for (int mi = 0; mi < 4; mi++) {
        const int i = i0 + wA * 64 + mi * 16 + g;
        #pragma unroll
        for (int nj = 0; nj < 2; nj++) {
            const int c = wB * 16 + nj * 8 + 2 * t4;
            float2 p0; p0.x = acc_o[mi][nj][0]; p0.y = acc_o[mi][nj][1];
            float2 p1; p1.x = acc_o[mi][nj][2]; p1.y = acc_o[mi][nj][3];
            *(float2*)&o[(size_t)(b * SS + i) * DMODEL + h * 64 + c] = p0;
            *(float2*)&o[(size_t)(b * SS + i + 8) * DMODEL + h * 64 + c] = p1;
        }
    }
}

// ---------------- scale final: g_scale[bh] = nz / Z ----------------
__global__ void __launch_bounds__(32) scale_final_kernel() {
    const int bh = blockIdx.x;
    const int lane = threadIdx.x;
    float s = (lane < 8) ? g_ps[bh * 8 + lane] : 0.f;
    #pragma unroll
    for (int off = 4; off; off >>= 1)
        s += __shfl_down_sync(0xFFFFFFFF, s, off);
    if (lane == 0) g_scale[bh] = g_nz / s;
}

// ---------------- out = LayerNorm(a + r) * gamma + beta ----------------
__global__ void __launch_bounds__(256) add_ln_kernel(
    const float* __restrict__ a, const float* __restrict__ r,
    const float* __restrict__ gam, const float* __restrict__ bet,
    float* __restrict__ o)
{
    __shared__ float red[256];
    const int row = blockIdx.x, t = threadIdx.x;
    const size_t base = (size_t)row * DMODEL;
    float y0 = a[base + t] + r[base + t];
    float y1 = a[base + t + 256] + r[base + t + 256];
    red[t] = y0 + y1; __syncthreads();
    for (int off = 128; off; off >>= 1) {
        if (t < off) red[t] += red[t + off];
        __syncthreads();
    }
    float mean = red[0] * (1.0f / DMODEL);
    __syncthreads();
    float d0 = y0 - mean, d1 = y1 - mean;
    red[t] = d0 * d0 + d1 * d1; __syncthreads();
    for (int off = 128; off; off >>= 1) {
        if (t < off) red[t] += red[t + off];
        __syncthreads();
    }
    float inv = rsqrtf(red[0] * (1.0f / DMODEL) + 1e-9f);
    o[base + t] = d0 * inv * gam[t] + bet[t];
    o[base + t + 256] = d1 * inv * gam[t + 256] + bet[t + 256];
}

// ---------------- host launcher ----------------
extern "C" void kernel_launch(void* const* d_in, const int* in_sizes, int n_in,
                              void* d_out, int out_size)
{
    (void)in_sizes; (void)n_in; (void)out_size;
    const float* x     = (const float*)d_in[0];
    const float* mask  = (const float*)d_in[1];
    const int*   ptk   = (const int*)d_in[2];
    const float* wq    = (const float*)d_in[3];
    const float* bq    = (const float*)d_in[4];
    const float* wk    = (const float*)d_in[5];
    const float* bk    = (const float*)d_in[6];
    const float* wv    = (const float*)d_in[7];
    const float* bv    = (const float*)d_in[8];
    const float* wo    = (const float*)d_in[9];
    const float* bo    = (const float*)d_in[10];
    const float* w1    = (const float*)d_in[11];
    const float* b1    = (const float*)d_in[12];
    const float* w2    = (const float*)d_in[13];
    const float* b2    = (const float*)d_in[14];
    const float* ln1g  = (const float*)d_in[15];
    const float* ln1b  = (const float*)d_in[16];
    const float* ln2g  = (const float*)d_in[17];
    const float* ln2b  = (const float*)d_in[18];
    float* out = (float*)d_out;

    float *q, *k, *v, *o, *t0, *out1, *ffn1, *hbuf, *scl;
    cudaGetSymbolAddress((void**)&q,    g_q);
    cudaGetSymbolAddress((void**)&k,    g_k);
    cudaGetSymbolAddress((void**)&v,    g_v);
    cudaGetSymbolAddress((void**)&o,    g_o);
    cudaGetSymbolAddress((void**)&t0,   g_t0);
    cudaGetSymbolAddress((void**)&out1, g_out1);
    cudaGetSymbolAddress((void**)&ffn1, g_ffn1);
    cudaGetSymbolAddress((void**)&hbuf, g_h);
    cudaGetSymbolAddress((void**)&scl,  g_scale);

    const int FUSED_SMEM = (128 * 36 * 2 + 32 * 36 * 2 + 32 * 132 + 32 * 72) * 4;
    cudaFuncSetAttribute(fused_attn,
                         cudaFuncAttributeMaxDynamicSharedMemorySize, FUSED_SMEM);

    count_nz_kernel<<<1, 256>>>(ptk);

    const dim3 gqkv(DMODEL / 128, MROWS / 128, 3);   // (4, 32, 3)
    const dim3 g512(DMODEL / 128, MROWS / 128, 1);   // (4, 32)
    const dim3 gff(DFF / 128, MROWS / 128, 1);       // (16, 32)
    const dim3 gnm(8, BHTOT);                        // (8, 32)
    const dim3 gfa(SS / 128, BHTOT);                 // (8, 32)

    const float* hin = x;
    for (int l = 0; l < 2; l++) {
        float* hout = (l == 1) ? out : hbuf;

        gemm_tf32<false, false><<<gqkv, 256>>>(hin,
            wq, bq, q,  wk, bk, k,  wv, bv, v,  DMODEL, DMODEL, nullptr);

        qk_normmax_kernel<<<gnm, 256>>>(q, k);
        fused_attn<<<gfa, 256, FUSED_SMEM>>>(q, k, v, mask, o);
        scale_final_kernel<<<BHTOT, 32>>>();

        gemm_tf32<false, true><<<g512, 256>>>(o,
            wo, bo, t0,  wo, bo, t0,  wo, bo, t0,  DMODEL, DMODEL, scl);
        add_ln_kernel<<<MROWS, 256>>>(hin, t0, ln1g, ln1b, out1);

        gemm_tf32<true, false><<<gff, 256>>>(out1,
            w1, b1, ffn1,  w1, b1, ffn1,  w1, b1, ffn1,  DFF, DMODEL, nullptr);
        gemm_tf32<false, false><<<g512, 256>>>(ffn1,
            w2, b2, t0,  w2, b2, t0,  w2, b2, t0,  DMODEL, DFF, nullptr);
        add_ln_kernel<<<MROWS, 256>>>(out1, t0, ln2g, ln2b, hout);

        hin = hout;
    }
}